// round 2
// baseline (speedup 1.0000x reference)
#include <cuda_runtime.h>
#include <cstdint>

// Problem constants
#define B_   2
#define QL_  512
#define KL_  8192
#define D_   1024
#define H_   8
#define HD_  128

// Scratch (device globals — no allocations allowed)
__device__ float g_Q[B_ * QL_ * D_];   // 4 MB
__device__ float g_K[B_ * KL_ * D_];   // 64 MB
__device__ float g_V[B_ * KL_ * D_];   // 64 MB
__device__ float g_O[B_ * QL_ * D_];   // 4 MB

// ---------------------------------------------------------------------------
// Generic NT GEMM + bias:  C[M,N] = A[M,K] @ W[N,K]^T + bias[N]
// Tile: BM=128, BN=64, BK=16. 256 threads, each computes 8x4.
// ---------------------------------------------------------------------------
__global__ __launch_bounds__(256) void gemm_nt_bias(
    const float* __restrict__ A, const float* __restrict__ W,
    const float* __restrict__ bias, float* __restrict__ C,
    int M, int N, int K)
{
    __shared__ float As[16][128];   // [k][m]
    __shared__ float Bs[16][68];    // [k][n], padded to 68 (float4-aligned rows)

    const int t  = threadIdx.x;
    const int m0 = blockIdx.y * 128;
    const int n0 = blockIdx.x * 64;
    const int ty = t >> 4;          // 0..15
    const int tx = t & 15;          // 0..15
    const int row_base = ty * 8;    // 0..120
    const int col_base = tx * 4;    // 0..60

    float acc[8][4];
#pragma unroll
    for (int i = 0; i < 8; i++)
#pragma unroll
        for (int j = 0; j < 4; j++) acc[i][j] = 0.f;

    for (int k0 = 0; k0 < K; k0 += 16) {
        // Load A tile: 128x16 = 512 float4, 2 per thread, stored transposed
#pragma unroll
        for (int c = 0; c < 2; ++c) {
            int v  = t + c * 256;           // 0..511
            int r  = v >> 2;                // row 0..127
            int kk = (v & 3) << 2;          // 0,4,8,12
            float4 a = *(const float4*)(A + (size_t)(m0 + r) * K + k0 + kk);
            As[kk + 0][r] = a.x; As[kk + 1][r] = a.y;
            As[kk + 2][r] = a.z; As[kk + 3][r] = a.w;
        }
        // Load W tile: 64x16 = 256 float4, 1 per thread, stored transposed
        {
            int r  = t >> 2;                // 0..63
            int kk = (t & 3) << 2;
            float4 b = *(const float4*)(W + (size_t)(n0 + r) * K + k0 + kk);
            Bs[kk + 0][r] = b.x; Bs[kk + 1][r] = b.y;
            Bs[kk + 2][r] = b.z; Bs[kk + 3][r] = b.w;
        }
        __syncthreads();

#pragma unroll
        for (int k = 0; k < 16; ++k) {
            float4 b4 = *(const float4*)&Bs[k][col_base];
            float4 a0 = *(const float4*)&As[k][row_base];
            float4 a1 = *(const float4*)&As[k][row_base + 4];
            float av[8] = {a0.x, a0.y, a0.z, a0.w, a1.x, a1.y, a1.z, a1.w};
            float bv[4] = {b4.x, b4.y, b4.z, b4.w};
#pragma unroll
            for (int i = 0; i < 8; i++)
#pragma unroll
                for (int j = 0; j < 4; j++)
                    acc[i][j] += av[i] * bv[j];
        }
        __syncthreads();
    }

    float4 bb = *(const float4*)(bias + n0 + col_base);
#pragma unroll
    for (int i = 0; i < 8; i++) {
        float4 o = make_float4(acc[i][0] + bb.x, acc[i][1] + bb.y,
                               acc[i][2] + bb.z, acc[i][3] + bb.w);
        *(float4*)(C + (size_t)(m0 + row_base + i) * N + n0 + col_base) = o;
    }
}

// ---------------------------------------------------------------------------
// Flash attention (fp32, online softmax), mask semantics matching reference:
// masked scores = -1e30; fully-masked rows -> output 0 ("wipe").
// Grid: (B*H, QL/64). Block: 256 threads = 8 warps. Each warp owns 8 q-rows.
// KV tiles of 32 rows; lane j owns kv column j of the tile.
// Mask is int32 (harness widens bool inputs to int32).
// ---------------------------------------------------------------------------
#define KPAD 132   // padded row stride (floats) for K/V tiles: conflict-free
#define FLASH_SMEM ((64 * 128 + 2 * 32 * KPAD) * 4)

__global__ __launch_bounds__(256) void flash_attn(
    const int* __restrict__ mask, float* __restrict__ O)
{
    extern __shared__ float sm[];
    float* Qs = sm;                    // [64][128]
    float* Ks = sm + 64 * 128;         // [32][KPAD]
    float* Vs = Ks + 32 * KPAD;        // [32][KPAD]

    const int b    = blockIdx.x >> 3;
    const int h    = blockIdx.x & 7;
    const int q0   = blockIdx.y * 64;
    const int t    = threadIdx.x;
    const int w    = t >> 5;
    const int lane = t & 31;
    const int qr0  = w * 8;

    // Load Q tile [64][128]: 2048 float4, 8 per thread
#pragma unroll
    for (int c = 0; c < 8; ++c) {
        int v  = t + c * 256;
        int r  = v >> 5;
        int d4 = (v & 31) << 2;
        *(float4*)(Qs + r * 128 + d4) =
            *(const float4*)(g_Q + (size_t)(b * QL_ + q0 + r) * D_ + h * HD_ + d4);
    }

    float acc[8][4];
    float mrow[8], lrow[8];
#pragma unroll
    for (int i = 0; i < 8; i++) {
        mrow[i] = -1e30f; lrow[i] = 0.f;
#pragma unroll
        for (int j = 0; j < 4; j++) acc[i][j] = 0.f;
    }

    const float scale = 0.08838834764831845f;   // 1/sqrt(128)

    for (int kv0 = 0; kv0 < KL_; kv0 += 32) {
        __syncthreads();
        // Load K,V tiles: 32x128 each = 1024 float4 each, 4 per thread each
#pragma unroll
        for (int c = 0; c < 4; ++c) {
            int v  = t + c * 256;
            int r  = v >> 5;
            int d4 = (v & 31) << 2;
            size_t goff = (size_t)(b * KL_ + kv0 + r) * D_ + h * HD_ + d4;
            *(float4*)(Ks + r * KPAD + d4) = *(const float4*)(g_K + goff);
            *(float4*)(Vs + r * KPAD + d4) = *(const float4*)(g_V + goff);
        }
        __syncthreads();

        // Scores: s[i] = Q[qr0+i] . K[lane]
        float s[8];
#pragma unroll
        for (int i = 0; i < 8; i++) s[i] = 0.f;
#pragma unroll 8
        for (int d4 = 0; d4 < 128; d4 += 4) {
            float4 k4 = *(const float4*)(Ks + lane * KPAD + d4);
#pragma unroll
            for (int i = 0; i < 8; i++) {
                float4 q4 = *(const float4*)(Qs + (qr0 + i) * 128 + d4);
                s[i] += q4.x * k4.x;
                s[i] += q4.y * k4.y;
                s[i] += q4.z * k4.z;
                s[i] += q4.w * k4.w;
            }
        }

        // Mask + online softmax per q-row (warp-exclusive rows)
#pragma unroll
        for (int i = 0; i < 8; i++) {
            int q = q0 + qr0 + i;
            int mk = mask[(size_t)(b * QL_ + q) * KL_ + kv0 + lane];
            float sv = mk ? s[i] * scale : -1e30f;
            float mx = sv;
#pragma unroll
            for (int o = 16; o; o >>= 1)
                mx = fmaxf(mx, __shfl_xor_sync(0xffffffffu, mx, o));
            float mnew = fmaxf(mrow[i], mx);
            float p    = __expf(sv - mnew);       // all-masked: exp(0)=1, later annihilated
            float fac  = __expf(mrow[i] - mnew);
            float ps   = p;
#pragma unroll
            for (int o = 16; o; o >>= 1)
                ps += __shfl_xor_sync(0xffffffffu, ps, o);
            lrow[i] = lrow[i] * fac + ps;
            mrow[i] = mnew;
            s[i]    = p;
#pragma unroll
            for (int j = 0; j < 4; j++) acc[i][j] *= fac;
        }

        // PV: acc[i][dd] += sum_kv p[i,kv] * V[kv][lane + 32*dd]
#pragma unroll 4
        for (int kv = 0; kv < 32; ++kv) {
            float pv[8];
#pragma unroll
            for (int i = 0; i < 8; i++)
                pv[i] = __shfl_sync(0xffffffffu, s[i], kv);
#pragma unroll
            for (int j = 0; j < 4; j++) {
                float vv = Vs[kv * KPAD + lane + j * 32];
#pragma unroll
                for (int i = 0; i < 8; i++) acc[i][j] += pv[i] * vv;
            }
        }
    }

    // Epilogue: normalize; wipe fully-masked rows to 0 (matches reference)
#pragma unroll
    for (int i = 0; i < 8; i++) {
        int q = q0 + qr0 + i;
        float invl = (mrow[i] <= -1e29f) ? 0.f : 1.0f / lrow[i];
#pragma unroll
        for (int j = 0; j < 4; j++)
            O[(size_t)(b * QL_ + q) * D_ + h * HD_ + lane + j * 32] = acc[i][j] * invl;
    }
}

// ---------------------------------------------------------------------------
// Launch: 3 projection GEMMs -> flash attention -> output GEMM
// ---------------------------------------------------------------------------
extern "C" void kernel_launch(void* const* d_in, const int* in_sizes, int n_in,
                              void* d_out, int out_size)
{
    const float* inq  = (const float*)d_in[0];
    const float* ink  = (const float*)d_in[1];
    const float* invv = (const float*)d_in[2];
    const int*   mask = (const int*)d_in[3];
    const float* Wq = (const float*)d_in[4];
    const float* bq = (const float*)d_in[5];
    const float* Wk = (const float*)d_in[6];
    const float* bk = (const float*)d_in[7];
    const float* Wv = (const float*)d_in[8];
    const float* bv = (const float*)d_in[9];
    const float* Wf = (const float*)d_in[10];
    const float* bf = (const float*)d_in[11];
    float* out = (float*)d_out;

    float *Qp, *Kp, *Vp, *Op;
    cudaGetSymbolAddress((void**)&Qp, g_Q);
    cudaGetSymbolAddress((void**)&Kp, g_K);
    cudaGetSymbolAddress((void**)&Vp, g_V);
    cudaGetSymbolAddress((void**)&Op, g_O);

    cudaFuncSetAttribute(flash_attn,
                         cudaFuncAttributeMaxDynamicSharedMemorySize, FLASH_SMEM);

    // Projections
    gemm_nt_bias<<<dim3(D_ / 64, (B_ * QL_) / 128), 256>>>(inq, Wq, bq, Qp, B_ * QL_, D_, D_);
    gemm_nt_bias<<<dim3(D_ / 64, (B_ * KL_) / 128), 256>>>(ink, Wk, bk, Kp, B_ * KL_, D_, D_);
    gemm_nt_bias<<<dim3(D_ / 64, (B_ * KL_) / 128), 256>>>(invv, Wv, bv, Vp, B_ * KL_, D_, D_);

    // Attention
    flash_attn<<<dim3(B_ * H_, QL_ / 64), 256, FLASH_SMEM>>>(mask, Op);

    // Output projection
    gemm_nt_bias<<<dim3(D_ / 64, (B_ * QL_) / 128), 256>>>(Op, Wf, bf, out, B_ * QL_, D_, D_);
}

// round 4
// speedup vs baseline: 1.5024x; 1.5024x over previous
#include <cuda_runtime.h>
#include <cstdint>

// Problem constants
#define B_   2
#define QL_  512
#define KL_  8192
#define D_   1024
#define H_   8
#define HD_  128

// Scratch (device globals — no allocations allowed)
__device__ float g_Q[B_ * QL_ * D_];
__device__ float g_K[B_ * KL_ * D_];
__device__ float g_V[B_ * KL_ * D_];
__device__ float g_O[B_ * QL_ * D_];

// fp32 -> tf32 round-to-nearest (unbiased; truncation would bias ~-5e-4)
__device__ __forceinline__ uint32_t tf32r(float x) {
    uint32_t u;
    asm("cvt.rna.tf32.f32 %0, %1;" : "=r"(u) : "f"(x));
    return u;
}

// m16n8k8 tf32 MMA (baseline PTX, compiles for plain sm_103)
__device__ __forceinline__ void mma_tf32(float* c, const uint32_t* a,
                                         const uint32_t* b) {
    asm volatile(
        "mma.sync.aligned.m16n8k8.row.col.f32.tf32.tf32.f32 "
        "{%0,%1,%2,%3}, {%4,%5,%6,%7}, {%8,%9}, {%0,%1,%2,%3};"
        : "+f"(c[0]), "+f"(c[1]), "+f"(c[2]), "+f"(c[3])
        : "r"(a[0]), "r"(a[1]), "r"(a[2]), "r"(a[3]), "r"(b[0]), "r"(b[1]));
}

// ===========================================================================
// tf32 mma.sync GEMM:  C[M,N] = rna_tf32(A[M,K]) @ rna_tf32(W[N,K])^T + bias
// CTA tile 128x128, K chunks of 32, double-buffered SMEM [128][36] (padded:
// fragment LDS banks (36*g + t4) mod 32 are conflict-free).
// 8 warps (2 m x 4 n), warp tile 64x32 -> 16 MMA / k-step, 64 accum regs.
// ===========================================================================
#define KC    32
#define APAD  36
#define BUFW  (128 * APAD)               // words per buffer per operand
#define GEMM_SMEM (4 * BUFW * 4)         // 73728 bytes

__global__ __launch_bounds__(256) void gemm_tf32(
    const float* __restrict__ A, const float* __restrict__ W,
    const float* __restrict__ bias, float* __restrict__ C,
    int M, int N, int K)
{
    extern __shared__ __align__(16) uint32_t sg[];
    uint32_t* As = sg;               // [2][BUFW]
    uint32_t* Bs = sg + 2 * BUFW;    // [2][BUFW]

    const int t = threadIdx.x, wid = t >> 5, lane = t & 31;
    const int g = lane >> 2, t4 = lane & 3;
    const int m0 = blockIdx.y * 128, n0 = blockIdx.x * 128;
    const int mw = (wid >> 2) * 64;  // 0 or 64
    const int nw = (wid & 3) * 32;   // 0,32,64,96

    float acc[4][4][4];
#pragma unroll
    for (int mt = 0; mt < 4; mt++)
#pragma unroll
        for (int nt = 0; nt < 4; nt++)
#pragma unroll
            for (int q = 0; q < 4; q++) acc[mt][nt][q] = 0.f;

    // Load geometry: 256 threads x 4 float4 cover a 128x32 chunk.
    const int r  = t >> 3;           // 0..31 (rows r, r+32, r+64, r+96)
    const int c4 = (t & 7) * 4;      // 0..28
    size_t gA[4], gB[4];
    int    so[4];
#pragma unroll
    for (int i = 0; i < 4; i++) {
        int ri = r + i * 32;
        gA[i] = (size_t)(m0 + ri) * K + c4;
        gB[i] = (size_t)(n0 + ri) * K + c4;
        so[i] = ri * APAD + c4;      // multiple of 4 words -> 16B aligned
    }

    const int NC = K / KC;
    float4 ra[4], rb[4];

    // Prologue: chunk 0 -> buf0, prefetch chunk 1 into regs
#pragma unroll
    for (int i = 0; i < 4; i++) {
        ra[i] = *(const float4*)(A + gA[i]);
        rb[i] = *(const float4*)(W + gB[i]);
    }
#pragma unroll
    for (int i = 0; i < 4; i++) {
        *(uint4*)(As + so[i]) = make_uint4(tf32r(ra[i].x), tf32r(ra[i].y),
                                           tf32r(ra[i].z), tf32r(ra[i].w));
        *(uint4*)(Bs + so[i]) = make_uint4(tf32r(rb[i].x), tf32r(rb[i].y),
                                           tf32r(rb[i].z), tf32r(rb[i].w));
    }
#pragma unroll
    for (int i = 0; i < 4; i++) {
        ra[i] = *(const float4*)(A + gA[i] + KC);
        rb[i] = *(const float4*)(W + gB[i] + KC);
    }
    __syncthreads();

    for (int c = 0; c < NC; c++) {
        const int buf = c & 1;
        if (c + 1 < NC) {
            uint32_t* Ad = As + (buf ^ 1) * BUFW;
            uint32_t* Bd = Bs + (buf ^ 1) * BUFW;
#pragma unroll
            for (int i = 0; i < 4; i++) {
                *(uint4*)(Ad + so[i]) = make_uint4(tf32r(ra[i].x), tf32r(ra[i].y),
                                                   tf32r(ra[i].z), tf32r(ra[i].w));
                *(uint4*)(Bd + so[i]) = make_uint4(tf32r(rb[i].x), tf32r(rb[i].y),
                                                   tf32r(rb[i].z), tf32r(rb[i].w));
            }
            if (c + 2 < NC) {
                const int k2 = (c + 2) * KC;
#pragma unroll
                for (int i = 0; i < 4; i++) {
                    ra[i] = *(const float4*)(A + gA[i] + k2);
                    rb[i] = *(const float4*)(W + gB[i] + k2);
                }
            }
            __syncthreads();   // STS(buf^1) visible before next iter's compute
        }

        // Compute chunk c from buf
        const uint32_t* Ab = As + buf * BUFW;
        const uint32_t* Bb = Bs + buf * BUFW;
#pragma unroll
        for (int ks = 0; ks < 4; ks++) {
            const int kb = ks * 8;
            uint32_t af[4][4], bf[4][2];
#pragma unroll
            for (int mt = 0; mt < 4; mt++) {
                const uint32_t* p = Ab + (mw + mt * 16 + g) * APAD + kb + t4;
                af[mt][0] = p[0];
                af[mt][1] = p[8 * APAD];
                af[mt][2] = p[4];
                af[mt][3] = p[8 * APAD + 4];
            }
#pragma unroll
            for (int nt = 0; nt < 4; nt++) {
                const uint32_t* p = Bb + (nw + nt * 8 + g) * APAD + kb + t4;
                bf[nt][0] = p[0];
                bf[nt][1] = p[4];
            }
#pragma unroll
            for (int mt = 0; mt < 4; mt++)
#pragma unroll
                for (int nt = 0; nt < 4; nt++)
                    mma_tf32(acc[mt][nt], af[mt], bf[nt]);
        }
        __syncthreads();       // done reading buf before iter c+1 overwrites it
    }

    // Epilogue: c0,c1 -> (row, col..col+1); c2,c3 -> (row+8, ...)
#pragma unroll
    for (int mt = 0; mt < 4; mt++) {
#pragma unroll
        for (int nt = 0; nt < 4; nt++) {
            const int row = m0 + mw + mt * 16 + g;
            const int col = n0 + nw + nt * 8 + 2 * t4;
            float2 bb = *(const float2*)(bias + col);
            *(float2*)(C + (size_t)row * N + col) =
                make_float2(acc[mt][nt][0] + bb.x, acc[mt][nt][1] + bb.y);
            *(float2*)(C + (size_t)(row + 8) * N + col) =
                make_float2(acc[mt][nt][2] + bb.x, acc[mt][nt][3] + bb.y);
        }
    }
}

// ===========================================================================
// Flash attention (fp32, online softmax) — unchanged from passing R2 version.
// ===========================================================================
#define KPAD 132
#define FLASH_SMEM ((64 * 128 + 2 * 32 * KPAD) * 4)

__global__ __launch_bounds__(256) void flash_attn(
    const int* __restrict__ mask, float* __restrict__ O)
{
    extern __shared__ float smf[];
    float* Qs = smf;
    float* Ks = smf + 64 * 128;
    float* Vs = Ks + 32 * KPAD;

    const int b    = blockIdx.x >> 3;
    const int h    = blockIdx.x & 7;
    const int q0   = blockIdx.y * 64;
    const int t    = threadIdx.x;
    const int w    = t >> 5;
    const int lane = t & 31;
    const int qr0  = w * 8;

#pragma unroll
    for (int c = 0; c < 8; ++c) {
        int v  = t + c * 256;
        int r  = v >> 5;
        int d4 = (v & 31) << 2;
        *(float4*)(Qs + r * 128 + d4) =
            *(const float4*)(g_Q + (size_t)(b * QL_ + q0 + r) * D_ + h * HD_ + d4);
    }

    float acc[8][4];
    float mrow[8], lrow[8];
#pragma unroll
    for (int i = 0; i < 8; i++) {
        mrow[i] = -1e30f; lrow[i] = 0.f;
#pragma unroll
        for (int j = 0; j < 4; j++) acc[i][j] = 0.f;
    }

    const float scale = 0.08838834764831845f;

    for (int kv0 = 0; kv0 < KL_; kv0 += 32) {
        __syncthreads();
#pragma unroll
        for (int c = 0; c < 4; ++c) {
            int v  = t + c * 256;
            int r  = v >> 5;
            int d4 = (v & 31) << 2;
            size_t goff = (size_t)(b * KL_ + kv0 + r) * D_ + h * HD_ + d4;
            *(float4*)(Ks + r * KPAD + d4) = *(const float4*)(g_K + goff);
            *(float4*)(Vs + r * KPAD + d4) = *(const float4*)(g_V + goff);
        }
        __syncthreads();

        float s[8];
#pragma unroll
        for (int i = 0; i < 8; i++) s[i] = 0.f;
#pragma unroll 8
        for (int d4 = 0; d4 < 128; d4 += 4) {
            float4 k4 = *(const float4*)(Ks + lane * KPAD + d4);
#pragma unroll
            for (int i = 0; i < 8; i++) {
                float4 q4 = *(const float4*)(Qs + (qr0 + i) * 128 + d4);
                s[i] += q4.x * k4.x;
                s[i] += q4.y * k4.y;
                s[i] += q4.z * k4.z;
                s[i] += q4.w * k4.w;
            }
        }

#pragma unroll
        for (int i = 0; i < 8; i++) {
            int q = q0 + qr0 + i;
            int mk = mask[(size_t)(b * QL_ + q) * KL_ + kv0 + lane];
            float sv = mk ? s[i] * scale : -1e30f;
            float mx = sv;
#pragma unroll
            for (int o = 16; o; o >>= 1)
                mx = fmaxf(mx, __shfl_xor_sync(0xffffffffu, mx, o));
            float mnew = fmaxf(mrow[i], mx);
            float p    = __expf(sv - mnew);
            float fac  = __expf(mrow[i] - mnew);
            float ps   = p;
#pragma unroll
            for (int o = 16; o; o >>= 1)
                ps += __shfl_xor_sync(0xffffffffu, ps, o);
            lrow[i] = lrow[i] * fac + ps;
            mrow[i] = mnew;
            s[i]    = p;
#pragma unroll
            for (int j = 0; j < 4; j++) acc[i][j] *= fac;
        }

#pragma unroll 4
        for (int kv = 0; kv < 32; ++kv) {
            float pv[8];
#pragma unroll
            for (int i = 0; i < 8; i++)
                pv[i] = __shfl_sync(0xffffffffu, s[i], kv);
#pragma unroll
            for (int j = 0; j < 4; j++) {
                float vv = Vs[kv * KPAD + lane + j * 32];
#pragma unroll
                for (int i = 0; i < 8; i++) acc[i][j] += pv[i] * vv;
            }
        }
    }

#pragma unroll
    for (int i = 0; i < 8; i++) {
        int q = q0 + qr0 + i;
        float invl = (mrow[i] <= -1e29f) ? 0.f : 1.0f / lrow[i];
#pragma unroll
        for (int j = 0; j < 4; j++)
            O[(size_t)(b * QL_ + q) * D_ + h * HD_ + lane + j * 32] = acc[i][j] * invl;
    }
}

// ===========================================================================
// Launch
// ===========================================================================
extern "C" void kernel_launch(void* const* d_in, const int* in_sizes, int n_in,
                              void* d_out, int out_size)
{
    const float* inq  = (const float*)d_in[0];
    const float* ink  = (const float*)d_in[1];
    const float* invv = (const float*)d_in[2];
    const int*   mask = (const int*)d_in[3];
    const float* Wq = (const float*)d_in[4];
    const float* bq = (const float*)d_in[5];
    const float* Wk = (const float*)d_in[6];
    const float* bk = (const float*)d_in[7];
    const float* Wv = (const float*)d_in[8];
    const float* bv = (const float*)d_in[9];
    const float* Wf = (const float*)d_in[10];
    const float* bf = (const float*)d_in[11];
    float* out = (float*)d_out;

    float *Qp, *Kp, *Vp, *Op;
    cudaGetSymbolAddress((void**)&Qp, g_Q);
    cudaGetSymbolAddress((void**)&Kp, g_K);
    cudaGetSymbolAddress((void**)&Vp, g_V);
    cudaGetSymbolAddress((void**)&Op, g_O);

    cudaFuncSetAttribute(gemm_tf32,
                         cudaFuncAttributeMaxDynamicSharedMemorySize, GEMM_SMEM);
    cudaFuncSetAttribute(flash_attn,
                         cudaFuncAttributeMaxDynamicSharedMemorySize, FLASH_SMEM);

    // Projections (mma.sync tf32)
    gemm_tf32<<<dim3(D_ / 128, (B_ * QL_) / 128), 256, GEMM_SMEM>>>(
        inq, Wq, bq, Qp, B_ * QL_, D_, D_);
    gemm_tf32<<<dim3(D_ / 128, (B_ * KL_) / 128), 256, GEMM_SMEM>>>(
        ink, Wk, bk, Kp, B_ * KL_, D_, D_);
    gemm_tf32<<<dim3(D_ / 128, (B_ * KL_) / 128), 256, GEMM_SMEM>>>(
        invv, Wv, bv, Vp, B_ * KL_, D_, D_);

    // Attention (SIMT fp32 — next round's target)
    flash_attn<<<dim3(B_ * H_, QL_ / 64), 256, FLASH_SMEM>>>(mask, Op);

    // Output projection
    gemm_tf32<<<dim3(D_ / 128, (B_ * QL_) / 128), 256, GEMM_SMEM>>>(
        Op, Wf, bf, out, B_ * QL_, D_, D_);
}

// round 6
// speedup vs baseline: 3.1829x; 2.1185x over previous
#include <cuda_runtime.h>
#include <cstdint>

// Problem constants
#define B_   2
#define QL_  512
#define KL_  8192
#define D_   1024
#define H_   8
#define HD_  128

// Scratch (device globals — no allocations allowed)
__device__ float g_Q[B_ * QL_ * D_];
__device__ float g_K[B_ * KL_ * D_];
__device__ float g_V[B_ * KL_ * D_];
__device__ float g_O[B_ * QL_ * D_];

// fp32 -> tf32 round-to-nearest (unbiased)
__device__ __forceinline__ uint32_t tf32r(float x) {
    uint32_t u;
    asm("cvt.rna.tf32.f32 %0, %1;" : "=r"(u) : "f"(x));
    return u;
}
__device__ __forceinline__ uint32_t smem_u32(const void* p) {
    uint32_t a;
    asm("{ .reg .u64 t; cvta.to.shared.u64 t, %1; cvt.u32.u64 %0, t; }"
        : "=r"(a) : "l"(p));
    return a;
}

// m16n8k8 tf32 MMA
__device__ __forceinline__ void mma_tf32(float* c, const uint32_t* a,
                                         const uint32_t* b) {
    asm volatile(
        "mma.sync.aligned.m16n8k8.row.col.f32.tf32.tf32.f32 "
        "{%0,%1,%2,%3}, {%4,%5,%6,%7}, {%8,%9}, {%0,%1,%2,%3};"
        : "+f"(c[0]), "+f"(c[1]), "+f"(c[2]), "+f"(c[3])
        : "r"(a[0]), "r"(a[1]), "r"(a[2]), "r"(a[3]), "r"(b[0]), "r"(b[1]));
}

#define CPA16(dst, src) \
    asm volatile("cp.async.cg.shared.global [%0], [%1], 16;" \
                 :: "r"(dst), "l"(src) : "memory")
#define CPA_COMMIT() asm volatile("cp.async.commit_group;" ::: "memory")
#define CPA_WAIT(n)  asm volatile("cp.async.wait_group %0;" :: "n"(n) : "memory")

// ===========================================================================
// tf32 mma.sync GEMM (unchanged from R4, passing):
// C[M,N] = rna_tf32(A[M,K]) @ rna_tf32(W[N,K])^T + bias
// ===========================================================================
#define KC    32
#define APAD  36
#define BUFW  (128 * APAD)
#define GEMM_SMEM (4 * BUFW * 4)

__global__ __launch_bounds__(256) void gemm_tf32(
    const float* __restrict__ A, const float* __restrict__ W,
    const float* __restrict__ bias, float* __restrict__ C,
    int M, int N, int K)
{
    extern __shared__ __align__(16) uint32_t sg[];
    uint32_t* As = sg;
    uint32_t* Bs = sg + 2 * BUFW;

    const int t = threadIdx.x, wid = t >> 5, lane = t & 31;
    const int g = lane >> 2, t4 = lane & 3;
    const int m0 = blockIdx.y * 128, n0 = blockIdx.x * 128;
    const int mw = (wid >> 2) * 64;
    const int nw = (wid & 3) * 32;

    float acc[4][4][4];
#pragma unroll
    for (int mt = 0; mt < 4; mt++)
#pragma unroll
        for (int nt = 0; nt < 4; nt++)
#pragma unroll
            for (int q = 0; q < 4; q++) acc[mt][nt][q] = 0.f;

    const int r  = t >> 3;
    const int c4 = (t & 7) * 4;
    size_t gA[4], gB[4];
    int    so[4];
#pragma unroll
    for (int i = 0; i < 4; i++) {
        int ri = r + i * 32;
        gA[i] = (size_t)(m0 + ri) * K + c4;
        gB[i] = (size_t)(n0 + ri) * K + c4;
        so[i] = ri * APAD + c4;
    }

    const int NC = K / KC;
    float4 ra[4], rb[4];

#pragma unroll
    for (int i = 0; i < 4; i++) {
        ra[i] = *(const float4*)(A + gA[i]);
        rb[i] = *(const float4*)(W + gB[i]);
    }
#pragma unroll
    for (int i = 0; i < 4; i++) {
        *(uint4*)(As + so[i]) = make_uint4(tf32r(ra[i].x), tf32r(ra[i].y),
                                           tf32r(ra[i].z), tf32r(ra[i].w));
        *(uint4*)(Bs + so[i]) = make_uint4(tf32r(rb[i].x), tf32r(rb[i].y),
                                           tf32r(rb[i].z), tf32r(rb[i].w));
    }
#pragma unroll
    for (int i = 0; i < 4; i++) {
        ra[i] = *(const float4*)(A + gA[i] + KC);
        rb[i] = *(const float4*)(W + gB[i] + KC);
    }
    __syncthreads();

    for (int c = 0; c < NC; c++) {
        const int buf = c & 1;
        if (c + 1 < NC) {
            uint32_t* Ad = As + (buf ^ 1) * BUFW;
            uint32_t* Bd = Bs + (buf ^ 1) * BUFW;
#pragma unroll
            for (int i = 0; i < 4; i++) {
                *(uint4*)(Ad + so[i]) = make_uint4(tf32r(ra[i].x), tf32r(ra[i].y),
                                                   tf32r(ra[i].z), tf32r(ra[i].w));
                *(uint4*)(Bd + so[i]) = make_uint4(tf32r(rb[i].x), tf32r(rb[i].y),
                                                   tf32r(rb[i].z), tf32r(rb[i].w));
            }
            if (c + 2 < NC) {
                const int k2 = (c + 2) * KC;
#pragma unroll
                for (int i = 0; i < 4; i++) {
                    ra[i] = *(const float4*)(A + gA[i] + k2);
                    rb[i] = *(const float4*)(W + gB[i] + k2);
                }
            }
            __syncthreads();
        }

        const uint32_t* Ab = As + buf * BUFW;
        const uint32_t* Bb = Bs + buf * BUFW;
#pragma unroll
        for (int ks = 0; ks < 4; ks++) {
            const int kb = ks * 8;
            uint32_t af[4][4], bf[4][2];
#pragma unroll
            for (int mt = 0; mt < 4; mt++) {
                const uint32_t* p = Ab + (mw + mt * 16 + g) * APAD + kb + t4;
                af[mt][0] = p[0];
                af[mt][1] = p[8 * APAD];
                af[mt][2] = p[4];
                af[mt][3] = p[8 * APAD + 4];
            }
#pragma unroll
            for (int nt = 0; nt < 4; nt++) {
                const uint32_t* p = Bb + (nw + nt * 8 + g) * APAD + kb + t4;
                bf[nt][0] = p[0];
                bf[nt][1] = p[4];
            }
#pragma unroll
            for (int mt = 0; mt < 4; mt++)
#pragma unroll
                for (int nt = 0; nt < 4; nt++)
                    mma_tf32(acc[mt][nt], af[mt], bf[nt]);
        }
        __syncthreads();
    }

#pragma unroll
    for (int mt = 0; mt < 4; mt++) {
#pragma unroll
        for (int nt = 0; nt < 4; nt++) {
            const int row = m0 + mw + mt * 16 + g;
            const int col = n0 + nw + nt * 8 + 2 * t4;
            float2 bb = *(const float2*)(bias + col);
            *(float2*)(C + (size_t)row * N + col) =
                make_float2(acc[mt][nt][0] + bb.x, acc[mt][nt][1] + bb.y);
            *(float2*)(C + (size_t)(row + 8) * N + col) =
                make_float2(acc[mt][nt][2] + bb.x, acc[mt][nt][3] + bb.y);
        }
    }
}

// ===========================================================================
// Flash attention on tensor cores (tf32 mma.sync).
// CTA: 64 q-rows of one (b,h). 8 warps = 4 q-groups x 2 kv-strips.
// KV tiles of 64 (strip 32/warp), double-buffered via cp.async.
// Per-warp independent online softmax over its strip; 2-way merge at end.
// Correct geometry (R5 fix): rows are FULL head dim (128 cols).
//   QP=KP=132 (132%32=4 -> frag banks 4g+t4 distinct)
//   VP=136    (136%32=8 -> frag banks 8t4+g distinct)
// SMEM words: Qs 64*132=8448 | Ks 2*8448=16896 | Vs 2*64*136=17408
//   total 42752 words = 171,008 B (1 CTA/SM).
// ===========================================================================
#define QT   64
#define KT   64
#define QP   132
#define KP   132
#define VP   136
#define KBUF 8448              // words per K buffer
#define VBUF 8704              // words per V buffer
#define FL_WORDS (8448 + 2 * KBUF + 2 * VBUF)   // 42752
#define FL_SMEM  (FL_WORDS * 4)                  // 171008

__global__ __launch_bounds__(256) void flash_mma(
    const int* __restrict__ mask, float* __restrict__ O)
{
    extern __shared__ __align__(16) uint32_t sf[];
    uint32_t* Qs = sf;
    uint32_t* Ks = sf + 8448;
    uint32_t* Vs = sf + 8448 + 2 * KBUF;
    const uint32_t sb   = smem_u32(sf);
    const uint32_t ks_b = sb + 8448 * 4;
    const uint32_t vs_b = sb + (8448 + 2 * KBUF) * 4;

    const int b  = blockIdx.x >> 3, h = blockIdx.x & 7;
    const int q0 = blockIdx.y * QT;
    const int t = threadIdx.x, wid = t >> 5, lane = t & 31;
    const int g = lane >> 2, t4 = lane & 3;
    const int qw = wid >> 1, kw = wid & 1;
    const int qrow = qw * 16 + g;                // warp-local q rows: qrow, qrow+8

    // Load Q tile -> tf32 smem
    {
        const size_t qbase = (size_t)(b * QL_ + q0) * D_ + h * HD_;
#pragma unroll
        for (int i = 0; i < 8; i++) {
            int v = t + i * 256, r = v >> 5, d4 = (v & 31) << 2;
            float4 q4 = *(const float4*)(g_Q + qbase + (size_t)r * D_ + d4);
            *(uint4*)(Qs + r * QP + d4) = make_uint4(tf32r(q4.x), tf32r(q4.y),
                                                     tf32r(q4.z), tf32r(q4.w));
        }
    }

    // KV load geometry (raw fp32 via cp.async; cvt at fragment load)
    const int lr  = t >> 5;          // 0..7 -> rows lr, lr+8, ... lr+56
    const int ld4 = (t & 31) << 2;   // word offset 0..124
    const size_t kvbase = (size_t)(b * KL_) * D_ + h * HD_;

    float acc[16][4];
#pragma unroll
    for (int dt = 0; dt < 16; dt++)
#pragma unroll
        for (int q = 0; q < 4; q++) acc[dt][q] = 0.f;
    float mrow[2] = {-1e30f, -1e30f}, lrow[2] = {0.f, 0.f};

    const float scale = 0.08838834764831845f;   // 1/sqrt(128)
    const int* mp0 = mask + (size_t)(b * QL_ + q0 + qrow) * KL_;
    const int* mp1 = mp0 + 8 * KL_;

    // prologue: tile 0 -> buf 0
#pragma unroll
    for (int i = 0; i < 8; i++) {
        int r = lr + i * 8;
        CPA16(ks_b + (r * KP + ld4) * 4, g_K + kvbase + (size_t)r * D_ + ld4);
    }
#pragma unroll
    for (int i = 0; i < 8; i++) {
        int r = lr + i * 8;
        CPA16(vs_b + (r * VP + ld4) * 4, g_V + kvbase + (size_t)r * D_ + ld4);
    }
    CPA_COMMIT();

    const int NT = KL_ / KT;   // 128
    for (int c = 0; c < NT; c++) {
        if (c + 1 < NT) {
            const int buf = (c + 1) & 1;
            const size_t rb = kvbase + (size_t)(c + 1) * KT * D_;
#pragma unroll
            for (int i = 0; i < 8; i++) {
                int r = lr + i * 8;
                CPA16(ks_b + (buf * KBUF + r * KP + ld4) * 4,
                      g_K + rb + (size_t)r * D_ + ld4);
            }
#pragma unroll
            for (int i = 0; i < 8; i++) {
                int r = lr + i * 8;
                CPA16(vs_b + (buf * VBUF + r * VP + ld4) * 4,
                      g_V + rb + (size_t)r * D_ + ld4);
            }
            CPA_COMMIT();
            CPA_WAIT(1);
        } else {
            CPA_WAIT(0);
        }
        __syncthreads();

        const uint32_t* Kb = Ks + (c & 1) * KBUF;
        const uint32_t* Vb = Vs + (c & 1) * VBUF;
        const int kvt = c * KT + kw * 32;

        // Prefetch mask for this tile (hide latency under the MMAs)
        int2 mk0[4], mk1[4];
#pragma unroll
        for (int nt = 0; nt < 4; nt++) {
            const int col = kvt + nt * 8 + 2 * t4;
            mk0[nt] = *(const int2*)(mp0 + col);
            mk1[nt] = *(const int2*)(mp1 + col);
        }

        // S = Q . K^T for this warp's strip (16q x 32kv)
        float s[4][4];
#pragma unroll
        for (int nt = 0; nt < 4; nt++)
#pragma unroll
            for (int q = 0; q < 4; q++) s[nt][q] = 0.f;
#pragma unroll
        for (int ks = 0; ks < 16; ks++) {
            const int kb = ks * 8;
            uint32_t af[4];
            const uint32_t* qp = Qs + qrow * QP + kb + t4;
            af[0] = qp[0];
            af[1] = qp[8 * QP];
            af[2] = qp[4];
            af[3] = qp[8 * QP + 4];
#pragma unroll
            for (int nt = 0; nt < 4; nt++) {
                const uint32_t* kp = Kb + (kw * 32 + nt * 8 + g) * KP + kb + t4;
                uint32_t bf[2] = { tf32r(__uint_as_float(kp[0])),
                                   tf32r(__uint_as_float(kp[4])) };
                mma_tf32(s[nt], af, bf);
            }
        }

        // mask + online softmax (rows qrow, qrow+8; quad-wide reductions)
        float mx0 = -1e30f, mx1 = -1e30f;
        float sv[4][4];
#pragma unroll
        for (int nt = 0; nt < 4; nt++) {
            sv[nt][0] = mk0[nt].x ? s[nt][0] * scale : -1e30f;
            sv[nt][1] = mk0[nt].y ? s[nt][1] * scale : -1e30f;
            sv[nt][2] = mk1[nt].x ? s[nt][2] * scale : -1e30f;
            sv[nt][3] = mk1[nt].y ? s[nt][3] * scale : -1e30f;
            mx0 = fmaxf(mx0, fmaxf(sv[nt][0], sv[nt][1]));
            mx1 = fmaxf(mx1, fmaxf(sv[nt][2], sv[nt][3]));
        }
#pragma unroll
        for (int o = 1; o <= 2; o <<= 1) {
            mx0 = fmaxf(mx0, __shfl_xor_sync(0xffffffffu, mx0, o));
            mx1 = fmaxf(mx1, __shfl_xor_sync(0xffffffffu, mx1, o));
        }
        const float mn0 = fmaxf(mrow[0], mx0), mn1 = fmaxf(mrow[1], mx1);
        const float f0 = __expf(mrow[0] - mn0), f1 = __expf(mrow[1] - mn1);
        float ps0 = 0.f, ps1 = 0.f;
#pragma unroll
        for (int nt = 0; nt < 4; nt++) {
            s[nt][0] = __expf(sv[nt][0] - mn0);
            s[nt][1] = __expf(sv[nt][1] - mn0);
            s[nt][2] = __expf(sv[nt][2] - mn1);
            s[nt][3] = __expf(sv[nt][3] - mn1);
            ps0 += s[nt][0] + s[nt][1];
            ps1 += s[nt][2] + s[nt][3];
        }
#pragma unroll
        for (int o = 1; o <= 2; o <<= 1) {
            ps0 += __shfl_xor_sync(0xffffffffu, ps0, o);
            ps1 += __shfl_xor_sync(0xffffffffu, ps1, o);
        }
        lrow[0] = lrow[0] * f0 + ps0;
        lrow[1] = lrow[1] * f1 + ps1;
        mrow[0] = mn0;
        mrow[1] = mn1;
#pragma unroll
        for (int dt = 0; dt < 16; dt++) {
            acc[dt][0] *= f0; acc[dt][1] *= f0;
            acc[dt][2] *= f1; acc[dt][3] *= f1;
        }

        // P (accum layout, cols {2t4,2t4+1}) -> A frags (cols {t4,t4+4}); PV
        const int srcA = (lane & ~3) | (t4 >> 1);
        const int srcB = srcA + 2;
        const bool odd = (t4 & 1);
#pragma unroll
        for (int ks = 0; ks < 4; ks++) {
            float v0a = __shfl_sync(0xffffffffu, s[ks][0], srcA);
            float v1a = __shfl_sync(0xffffffffu, s[ks][1], srcA);
            float v2a = __shfl_sync(0xffffffffu, s[ks][2], srcA);
            float v3a = __shfl_sync(0xffffffffu, s[ks][3], srcA);
            float v0b = __shfl_sync(0xffffffffu, s[ks][0], srcB);
            float v1b = __shfl_sync(0xffffffffu, s[ks][1], srcB);
            float v2b = __shfl_sync(0xffffffffu, s[ks][2], srcB);
            float v3b = __shfl_sync(0xffffffffu, s[ks][3], srcB);
            uint32_t af[4];
            af[0] = tf32r(odd ? v1a : v0a);
            af[1] = tf32r(odd ? v3a : v2a);
            af[2] = tf32r(odd ? v1b : v0b);
            af[3] = tf32r(odd ? v3b : v2b);
            const uint32_t* vp0 = Vb + (kw * 32 + ks * 8 + t4) * VP + g;
            const uint32_t* vp1 = vp0 + 4 * VP;
#pragma unroll
            for (int dt = 0; dt < 16; dt++) {
                uint32_t bf[2] = { tf32r(__uint_as_float(vp0[dt * 8])),
                                   tf32r(__uint_as_float(vp1[dt * 8])) };
                mma_tf32(acc[dt], af, bf);
            }
        }
        __syncthreads();
    }

    // ---- 2-way merge across kv-strips (overlay smem) ----
    __syncthreads();
    float* ab = (float*)sf;          // [64][130]
    float* ml = (float*)sf + 64 * 130;
    const int r0 = qw * 16 + g, r1 = r0 + 8;

    if (kw == 1) {
#pragma unroll
        for (int dt = 0; dt < 16; dt++) {
            const int cb = dt * 8 + 2 * t4;
            ab[r0 * 130 + cb]     = acc[dt][0];
            ab[r0 * 130 + cb + 1] = acc[dt][1];
            ab[r1 * 130 + cb]     = acc[dt][2];
            ab[r1 * 130 + cb + 1] = acc[dt][3];
        }
        if (t4 == 0) {
            ml[r0 * 2] = mrow[0]; ml[r0 * 2 + 1] = lrow[0];
            ml[r1 * 2] = mrow[1]; ml[r1 * 2 + 1] = lrow[1];
        }
    }
    __syncthreads();
    if (kw == 0) {
        const float m1a = ml[r0 * 2], l1a = ml[r0 * 2 + 1];
        const float m1b = ml[r1 * 2], l1b = ml[r1 * 2 + 1];
        const float mf0 = fmaxf(mrow[0], m1a), mf1 = fmaxf(mrow[1], m1b);
        const float e00 = __expf(mrow[0] - mf0), e01 = __expf(m1a - mf0);
        const float e10 = __expf(mrow[1] - mf1), e11 = __expf(m1b - mf1);
        const float lf0 = lrow[0] * e00 + l1a * e01;
        const float lf1 = lrow[1] * e10 + l1b * e11;
        const float i0 = (mf0 <= -1e29f) ? 0.f : 1.f / lf0;
        const float i1 = (mf1 <= -1e29f) ? 0.f : 1.f / lf1;
        float* o0p = O + (size_t)(b * QL_ + q0 + r0) * D_ + h * HD_;
        float* o1p = O + (size_t)(b * QL_ + q0 + r1) * D_ + h * HD_;
#pragma unroll
        for (int dt = 0; dt < 16; dt++) {
            const int cb = dt * 8 + 2 * t4;
            float x0 = (acc[dt][0] * e00 + ab[r0 * 130 + cb]     * e01) * i0;
            float x1 = (acc[dt][1] * e00 + ab[r0 * 130 + cb + 1] * e01) * i0;
            float x2 = (acc[dt][2] * e10 + ab[r1 * 130 + cb]     * e11) * i1;
            float x3 = (acc[dt][3] * e10 + ab[r1 * 130 + cb + 1] * e11) * i1;
            *(float2*)(o0p + cb) = make_float2(x0, x1);
            *(float2*)(o1p + cb) = make_float2(x2, x3);
        }
    }
}

// ===========================================================================
// Launch
// ===========================================================================
extern "C" void kernel_launch(void* const* d_in, const int* in_sizes, int n_in,
                              void* d_out, int out_size)
{
    const float* inq  = (const float*)d_in[0];
    const float* ink  = (const float*)d_in[1];
    const float* invv = (const float*)d_in[2];
    const int*   mask = (const int*)d_in[3];
    const float* Wq = (const float*)d_in[4];
    const float* bq = (const float*)d_in[5];
    const float* Wk = (const float*)d_in[6];
    const float* bk = (const float*)d_in[7];
    const float* Wv = (const float*)d_in[8];
    const float* bv = (const float*)d_in[9];
    const float* Wf = (const float*)d_in[10];
    const float* bf = (const float*)d_in[11];
    float* out = (float*)d_out;

    float *Qp, *Kp, *Vp, *Op;
    cudaGetSymbolAddress((void**)&Qp, g_Q);
    cudaGetSymbolAddress((void**)&Kp, g_K);
    cudaGetSymbolAddress((void**)&Vp, g_V);
    cudaGetSymbolAddress((void**)&Op, g_O);

    cudaFuncSetAttribute(gemm_tf32,
                         cudaFuncAttributeMaxDynamicSharedMemorySize, GEMM_SMEM);
    cudaFuncSetAttribute(flash_mma,
                         cudaFuncAttributeMaxDynamicSharedMemorySize, FL_SMEM);

    // Projections (mma.sync tf32)
    gemm_tf32<<<dim3(D_ / 128, (B_ * QL_) / 128), 256, GEMM_SMEM>>>(
        inq, Wq, bq, Qp, B_ * QL_, D_, D_);
    gemm_tf32<<<dim3(D_ / 128, (B_ * KL_) / 128), 256, GEMM_SMEM>>>(
        ink, Wk, bk, Kp, B_ * KL_, D_, D_);
    gemm_tf32<<<dim3(D_ / 128, (B_ * KL_) / 128), 256, GEMM_SMEM>>>(
        invv, Wv, bv, Vp, B_ * KL_, D_, D_);

    // Attention (tensor-core flash)
    flash_mma<<<dim3(B_ * H_, QL_ / QT), 256, FL_SMEM>>>(mask, Op);

    // Output projection
    gemm_tf32<<<dim3(D_ / 128, (B_ * QL_) / 128), 256, GEMM_SMEM>>>(
        Op, Wf, bf, out, B_ * QL_, D_, D_);
}

// round 7
// speedup vs baseline: 3.3010x; 1.0371x over previous
#include <cuda_runtime.h>
#include <cstdint>

// Problem constants
#define B_   2
#define QL_  512
#define KL_  8192
#define D_   1024
#define H_   8
#define HD_  128

// Scratch (device globals — no allocations allowed)
__device__ float g_Q[B_ * QL_ * D_];
__device__ float g_K[B_ * KL_ * D_];
__device__ float g_V[B_ * KL_ * D_];
__device__ float g_O[B_ * QL_ * D_];

// fp32 -> tf32 round-to-nearest (unbiased)
__device__ __forceinline__ uint32_t tf32r(float x) {
    uint32_t u;
    asm("cvt.rna.tf32.f32 %0, %1;" : "=r"(u) : "f"(x));
    return u;
}
__device__ __forceinline__ uint32_t smem_u32(const void* p) {
    uint32_t a;
    asm("{ .reg .u64 t; cvta.to.shared.u64 t, %1; cvt.u32.u64 %0, t; }"
        : "=r"(a) : "l"(p));
    return a;
}

// m16n8k8 tf32 MMA
__device__ __forceinline__ void mma_tf32(float* c, const uint32_t* a,
                                         const uint32_t* b) {
    asm volatile(
        "mma.sync.aligned.m16n8k8.row.col.f32.tf32.tf32.f32 "
        "{%0,%1,%2,%3}, {%4,%5,%6,%7}, {%8,%9}, {%0,%1,%2,%3};"
        : "+f"(c[0]), "+f"(c[1]), "+f"(c[2]), "+f"(c[3])
        : "r"(a[0]), "r"(a[1]), "r"(a[2]), "r"(a[3]), "r"(b[0]), "r"(b[1]));
}

#define CPA16(dst, src) \
    asm volatile("cp.async.cg.shared.global [%0], [%1], 16;" \
                 :: "r"(dst), "l"(src) : "memory")
#define CPA_COMMIT() asm volatile("cp.async.commit_group;" ::: "memory")
#define CPA_WAIT(n)  asm volatile("cp.async.wait_group %0;" :: "n"(n) : "memory")

// ===========================================================================
// tf32 mma.sync GEMM:  C = rna_tf32(A) @ rna_tf32(W)^T + bias
// round_store=1 -> output rounded to tf32 (for tensors consumed by flash).
// ===========================================================================
#define KC    32
#define APAD  36
#define BUFW  (128 * APAD)
#define GEMM_SMEM (4 * BUFW * 4)

__global__ __launch_bounds__(256) void gemm_tf32(
    const float* __restrict__ A, const float* __restrict__ W,
    const float* __restrict__ bias, float* __restrict__ C,
    int M, int N, int K, int round_store)
{
    extern __shared__ __align__(16) uint32_t sg[];
    uint32_t* As = sg;
    uint32_t* Bs = sg + 2 * BUFW;

    const int t = threadIdx.x, wid = t >> 5, lane = t & 31;
    const int g = lane >> 2, t4 = lane & 3;
    const int m0 = blockIdx.y * 128, n0 = blockIdx.x * 128;
    const int mw = (wid >> 2) * 64;
    const int nw = (wid & 3) * 32;

    float acc[4][4][4];
#pragma unroll
    for (int mt = 0; mt < 4; mt++)
#pragma unroll
        for (int nt = 0; nt < 4; nt++)
#pragma unroll
            for (int q = 0; q < 4; q++) acc[mt][nt][q] = 0.f;

    const int r  = t >> 3;
    const int c4 = (t & 7) * 4;
    size_t gA[4], gB[4];
    int    so[4];
#pragma unroll
    for (int i = 0; i < 4; i++) {
        int ri = r + i * 32;
        gA[i] = (size_t)(m0 + ri) * K + c4;
        gB[i] = (size_t)(n0 + ri) * K + c4;
        so[i] = ri * APAD + c4;
    }

    const int NC = K / KC;
    float4 ra[4], rb[4];

#pragma unroll
    for (int i = 0; i < 4; i++) {
        ra[i] = *(const float4*)(A + gA[i]);
        rb[i] = *(const float4*)(W + gB[i]);
    }
#pragma unroll
    for (int i = 0; i < 4; i++) {
        *(uint4*)(As + so[i]) = make_uint4(tf32r(ra[i].x), tf32r(ra[i].y),
                                           tf32r(ra[i].z), tf32r(ra[i].w));
        *(uint4*)(Bs + so[i]) = make_uint4(tf32r(rb[i].x), tf32r(rb[i].y),
                                           tf32r(rb[i].z), tf32r(rb[i].w));
    }
#pragma unroll
    for (int i = 0; i < 4; i++) {
        ra[i] = *(const float4*)(A + gA[i] + KC);
        rb[i] = *(const float4*)(W + gB[i] + KC);
    }
    __syncthreads();

    for (int c = 0; c < NC; c++) {
        const int buf = c & 1;
        if (c + 1 < NC) {
            uint32_t* Ad = As + (buf ^ 1) * BUFW;
            uint32_t* Bd = Bs + (buf ^ 1) * BUFW;
#pragma unroll
            for (int i = 0; i < 4; i++) {
                *(uint4*)(Ad + so[i]) = make_uint4(tf32r(ra[i].x), tf32r(ra[i].y),
                                                   tf32r(ra[i].z), tf32r(ra[i].w));
                *(uint4*)(Bd + so[i]) = make_uint4(tf32r(rb[i].x), tf32r(rb[i].y),
                                                   tf32r(rb[i].z), tf32r(rb[i].w));
            }
            if (c + 2 < NC) {
                const int k2 = (c + 2) * KC;
#pragma unroll
                for (int i = 0; i < 4; i++) {
                    ra[i] = *(const float4*)(A + gA[i] + k2);
                    rb[i] = *(const float4*)(W + gB[i] + k2);
                }
            }
            __syncthreads();
        }

        const uint32_t* Ab = As + buf * BUFW;
        const uint32_t* Bb = Bs + buf * BUFW;
#pragma unroll
        for (int ks = 0; ks < 4; ks++) {
            const int kb = ks * 8;
            uint32_t af[4][4], bf[4][2];
#pragma unroll
            for (int mt = 0; mt < 4; mt++) {
                const uint32_t* p = Ab + (mw + mt * 16 + g) * APAD + kb + t4;
                af[mt][0] = p[0];
                af[mt][1] = p[8 * APAD];
                af[mt][2] = p[4];
                af[mt][3] = p[8 * APAD + 4];
            }
#pragma unroll
            for (int nt = 0; nt < 4; nt++) {
                const uint32_t* p = Bb + (nw + nt * 8 + g) * APAD + kb + t4;
                bf[nt][0] = p[0];
                bf[nt][1] = p[4];
            }
#pragma unroll
            for (int mt = 0; mt < 4; mt++)
#pragma unroll
                for (int nt = 0; nt < 4; nt++)
                    mma_tf32(acc[mt][nt], af[mt], bf[nt]);
        }
        __syncthreads();
    }

#pragma unroll
    for (int mt = 0; mt < 4; mt++) {
#pragma unroll
        for (int nt = 0; nt < 4; nt++) {
            const int row = m0 + mw + mt * 16 + g;
            const int col = n0 + nw + nt * 8 + 2 * t4;
            float2 bb = *(const float2*)(bias + col);
            float o0 = acc[mt][nt][0] + bb.x, o1 = acc[mt][nt][1] + bb.y;
            float o2 = acc[mt][nt][2] + bb.x, o3 = acc[mt][nt][3] + bb.y;
            if (round_store) {
                o0 = __uint_as_float(tf32r(o0));
                o1 = __uint_as_float(tf32r(o1));
                o2 = __uint_as_float(tf32r(o2));
                o3 = __uint_as_float(tf32r(o3));
            }
            *(float2*)(C + (size_t)row * N + col) = make_float2(o0, o1);
            *(float2*)(C + (size_t)(row + 8) * N + col) = make_float2(o2, o3);
        }
    }
}

// ===========================================================================
// Flash attention on tensor cores (tf32 mma.sync).
// CTA: 64 q-rows of one (b,h). 8 warps = 4 q-groups x 2 kv-strips.
// KV tiles of 64 (strip 32/warp), double-buffered cp.async.
// Q/K/V arrive PRE-ROUNDED to tf32 (gemm round_store) -> raw fragment loads.
// PV uses permuted-V trick: P accumulator feeds MMA A directly; the
// col permutation (acc cols {2t4,2t4+1} vs A cols {t4,t4+4}) is absorbed
// by loading V rows {2t4, 2t4+1}. Zero shuffles.
// Pads: QP=KP=132 (banks 4g+t4, all distinct); VP=132 (new V pattern banks
// 8t4+g, all distinct).
// SMEM: 5 * 8448 words = 168,960 B (1 CTA/SM).
// ===========================================================================
#define QT   64
#define KT   64
#define QP   132
#define KP   132
#define VP   132
#define KBUF 8448
#define VBUF 8448
#define FL_WORDS (8448 + 2 * KBUF + 2 * VBUF)   // 42240
#define FL_SMEM  (FL_WORDS * 4)                  // 168960

__global__ __launch_bounds__(256) void flash_mma(
    const int* __restrict__ mask, float* __restrict__ O)
{
    extern __shared__ __align__(16) uint32_t sf[];
    uint32_t* Qs = sf;
    uint32_t* Ks = sf + 8448;
    uint32_t* Vs = sf + 8448 + 2 * KBUF;
    const uint32_t sb   = smem_u32(sf);
    const uint32_t ks_b = sb + 8448 * 4;
    const uint32_t vs_b = sb + (8448 + 2 * KBUF) * 4;

    const int b  = blockIdx.x >> 3, h = blockIdx.x & 7;
    const int q0 = blockIdx.y * QT;
    const int t = threadIdx.x, wid = t >> 5, lane = t & 31;
    const int g = lane >> 2, t4 = lane & 3;
    const int qw = wid >> 1, kw = wid & 1;
    const int qrow = qw * 16 + g;

    // Load Q tile (already tf32-rounded bits) -> smem
    {
        const size_t qbase = (size_t)(b * QL_ + q0) * D_ + h * HD_;
#pragma unroll
        for (int i = 0; i < 8; i++) {
            int v = t + i * 256, r = v >> 5, d4 = (v & 31) << 2;
            *(uint4*)(Qs + r * QP + d4) =
                *(const uint4*)(g_Q + qbase + (size_t)r * D_ + d4);
        }
    }

    const int lr  = t >> 5;
    const int ld4 = (t & 31) << 2;
    const size_t kvbase = (size_t)(b * KL_) * D_ + h * HD_;

    float acc[16][4];
#pragma unroll
    for (int dt = 0; dt < 16; dt++)
#pragma unroll
        for (int q = 0; q < 4; q++) acc[dt][q] = 0.f;
    float mrow[2] = {-1e30f, -1e30f}, lrow[2] = {0.f, 0.f};

    const float scale = 0.08838834764831845f;   // 1/sqrt(128)
    const int* mp0 = mask + (size_t)(b * QL_ + q0 + qrow) * KL_;
    const int* mp1 = mp0 + 8 * KL_;

    // prologue: tile 0 -> buf 0
#pragma unroll
    for (int i = 0; i < 8; i++) {
        int r = lr + i * 8;
        CPA16(ks_b + (r * KP + ld4) * 4, g_K + kvbase + (size_t)r * D_ + ld4);
    }
#pragma unroll
    for (int i = 0; i < 8; i++) {
        int r = lr + i * 8;
        CPA16(vs_b + (r * VP + ld4) * 4, g_V + kvbase + (size_t)r * D_ + ld4);
    }
    CPA_COMMIT();

    const int NT = KL_ / KT;   // 128
    for (int c = 0; c < NT; c++) {
        if (c + 1 < NT) {
            const int buf = (c + 1) & 1;
            const size_t rb = kvbase + (size_t)(c + 1) * KT * D_;
#pragma unroll
            for (int i = 0; i < 8; i++) {
                int r = lr + i * 8;
                CPA16(ks_b + (buf * KBUF + r * KP + ld4) * 4,
                      g_K + rb + (size_t)r * D_ + ld4);
            }
#pragma unroll
            for (int i = 0; i < 8; i++) {
                int r = lr + i * 8;
                CPA16(vs_b + (buf * VBUF + r * VP + ld4) * 4,
                      g_V + rb + (size_t)r * D_ + ld4);
            }
            CPA_COMMIT();
            CPA_WAIT(1);
        } else {
            CPA_WAIT(0);
        }
        __syncthreads();

        const uint32_t* Kb = Ks + (c & 1) * KBUF;
        const uint32_t* Vb = Vs + (c & 1) * VBUF;
        const int kvt = c * KT + kw * 32;

        // Prefetch mask for this tile
        int2 mk0[4], mk1[4];
#pragma unroll
        for (int nt = 0; nt < 4; nt++) {
            const int col = kvt + nt * 8 + 2 * t4;
            mk0[nt] = *(const int2*)(mp0 + col);
            mk1[nt] = *(const int2*)(mp1 + col);
        }

        // S = Q . K^T (raw tf32 bits from smem)
        float s[4][4];
#pragma unroll
        for (int nt = 0; nt < 4; nt++)
#pragma unroll
            for (int q = 0; q < 4; q++) s[nt][q] = 0.f;
#pragma unroll
        for (int ks = 0; ks < 16; ks++) {
            const int kb = ks * 8;
            uint32_t af[4];
            const uint32_t* qp = Qs + qrow * QP + kb + t4;
            af[0] = qp[0];
            af[1] = qp[8 * QP];
            af[2] = qp[4];
            af[3] = qp[8 * QP + 4];
#pragma unroll
            for (int nt = 0; nt < 4; nt++) {
                const uint32_t* kp = Kb + (kw * 32 + nt * 8 + g) * KP + kb + t4;
                uint32_t bf[2] = { kp[0], kp[4] };
                mma_tf32(s[nt], af, bf);
            }
        }

        // mask + online softmax (rows qrow, qrow+8; quad reductions)
        float mx0 = -1e30f, mx1 = -1e30f;
        float sv[4][4];
#pragma unroll
        for (int nt = 0; nt < 4; nt++) {
            sv[nt][0] = mk0[nt].x ? s[nt][0] * scale : -1e30f;
            sv[nt][1] = mk0[nt].y ? s[nt][1] * scale : -1e30f;
            sv[nt][2] = mk1[nt].x ? s[nt][2] * scale : -1e30f;
            sv[nt][3] = mk1[nt].y ? s[nt][3] * scale : -1e30f;
            mx0 = fmaxf(mx0, fmaxf(sv[nt][0], sv[nt][1]));
            mx1 = fmaxf(mx1, fmaxf(sv[nt][2], sv[nt][3]));
        }
#pragma unroll
        for (int o = 1; o <= 2; o <<= 1) {
            mx0 = fmaxf(mx0, __shfl_xor_sync(0xffffffffu, mx0, o));
            mx1 = fmaxf(mx1, __shfl_xor_sync(0xffffffffu, mx1, o));
        }
        const float mn0 = fmaxf(mrow[0], mx0), mn1 = fmaxf(mrow[1], mx1);
        const float f0 = __expf(mrow[0] - mn0), f1 = __expf(mrow[1] - mn1);
        float ps0 = 0.f, ps1 = 0.f;
#pragma unroll
        for (int nt = 0; nt < 4; nt++) {
            s[nt][0] = __expf(sv[nt][0] - mn0);
            s[nt][1] = __expf(sv[nt][1] - mn0);
            s[nt][2] = __expf(sv[nt][2] - mn1);
            s[nt][3] = __expf(sv[nt][3] - mn1);
            ps0 += s[nt][0] + s[nt][1];
            ps1 += s[nt][2] + s[nt][3];
        }
#pragma unroll
        for (int o = 1; o <= 2; o <<= 1) {
            ps0 += __shfl_xor_sync(0xffffffffu, ps0, o);
            ps1 += __shfl_xor_sync(0xffffffffu, ps1, o);
        }
        lrow[0] = lrow[0] * f0 + ps0;
        lrow[1] = lrow[1] * f1 + ps1;
        mrow[0] = mn0;
        mrow[1] = mn1;
#pragma unroll
        for (int dt = 0; dt < 16; dt++) {
            acc[dt][0] *= f0; acc[dt][1] *= f0;
            acc[dt][2] *= f1; acc[dt][3] *= f1;
        }

        // PV with permuted V rows (no shuffles):
        // a[0]=s[0] (row g, kv 2t4), a[1]=s[2] (row g+8, kv 2t4),
        // a[2]=s[1] (row g, kv 2t4+1), a[3]=s[3]; V rows 2t4, 2t4+1.
#pragma unroll
        for (int ks = 0; ks < 4; ks++) {
            uint32_t af[4];
            af[0] = tf32r(s[ks][0]);
            af[1] = tf32r(s[ks][2]);
            af[2] = tf32r(s[ks][1]);
            af[3] = tf32r(s[ks][3]);
            const uint32_t* vp0 = Vb + (kw * 32 + ks * 8 + 2 * t4) * VP + g;
            const uint32_t* vp1 = vp0 + VP;
#pragma unroll
            for (int dt = 0; dt < 16; dt++) {
                uint32_t bf[2] = { vp0[dt * 8], vp1[dt * 8] };
                mma_tf32(acc[dt], af, bf);
            }
        }
        __syncthreads();
    }

    // ---- 2-way merge across kv-strips (overlay smem in Qs region) ----
    __syncthreads();
    float* ab = (float*)sf;          // [64][130] = 8320 words
    float* ml = (float*)sf + 64 * 130;
    const int r0 = qw * 16 + g, r1 = r0 + 8;

    if (kw == 1) {
#pragma unroll
        for (int dt = 0; dt < 16; dt++) {
            const int cb = dt * 8 + 2 * t4;
            ab[r0 * 130 + cb]     = acc[dt][0];
            ab[r0 * 130 + cb + 1] = acc[dt][1];
            ab[r1 * 130 + cb]     = acc[dt][2];
            ab[r1 * 130 + cb + 1] = acc[dt][3];
        }
        if (t4 == 0) {
            ml[r0 * 2] = mrow[0]; ml[r0 * 2 + 1] = lrow[0];
            ml[r1 * 2] = mrow[1]; ml[r1 * 2 + 1] = lrow[1];
        }
    }
    __syncthreads();
    if (kw == 0) {
        const float m1a = ml[r0 * 2], l1a = ml[r0 * 2 + 1];
        const float m1b = ml[r1 * 2], l1b = ml[r1 * 2 + 1];
        const float mf0 = fmaxf(mrow[0], m1a), mf1 = fmaxf(mrow[1], m1b);
        const float e00 = __expf(mrow[0] - mf0), e01 = __expf(m1a - mf0);
        const float e10 = __expf(mrow[1] - mf1), e11 = __expf(m1b - mf1);
        const float lf0 = lrow[0] * e00 + l1a * e01;
        const float lf1 = lrow[1] * e10 + l1b * e11;
        const float i0 = (mf0 <= -1e29f) ? 0.f : 1.f / lf0;
        const float i1 = (mf1 <= -1e29f) ? 0.f : 1.f / lf1;
        float* o0p = O + (size_t)(b * QL_ + q0 + r0) * D_ + h * HD_;
        float* o1p = O + (size_t)(b * QL_ + q0 + r1) * D_ + h * HD_;
#pragma unroll
        for (int dt = 0; dt < 16; dt++) {
            const int cb = dt * 8 + 2 * t4;
            float x0 = (acc[dt][0] * e00 + ab[r0 * 130 + cb]     * e01) * i0;
            float x1 = (acc[dt][1] * e00 + ab[r0 * 130 + cb + 1] * e01) * i0;
            float x2 = (acc[dt][2] * e10 + ab[r1 * 130 + cb]     * e11) * i1;
            float x3 = (acc[dt][3] * e10 + ab[r1 * 130 + cb + 1] * e11) * i1;
            *(float2*)(o0p + cb) = make_float2(x0, x1);
            *(float2*)(o1p + cb) = make_float2(x2, x3);
        }
    }
}

// ===========================================================================
// Launch
// ===========================================================================
extern "C" void kernel_launch(void* const* d_in, const int* in_sizes, int n_in,
                              void* d_out, int out_size)
{
    const float* inq  = (const float*)d_in[0];
    const float* ink  = (const float*)d_in[1];
    const float* invv = (const float*)d_in[2];
    const int*   mask = (const int*)d_in[3];
    const float* Wq = (const float*)d_in[4];
    const float* bq = (const float*)d_in[5];
    const float* Wk = (const float*)d_in[6];
    const float* bk = (const float*)d_in[7];
    const float* Wv = (const float*)d_in[8];
    const float* bv = (const float*)d_in[9];
    const float* Wf = (const float*)d_in[10];
    const float* bf = (const float*)d_in[11];
    float* out = (float*)d_out;

    float *Qp, *Kp, *Vp, *Op;
    cudaGetSymbolAddress((void**)&Qp, g_Q);
    cudaGetSymbolAddress((void**)&Kp, g_K);
    cudaGetSymbolAddress((void**)&Vp, g_V);
    cudaGetSymbolAddress((void**)&Op, g_O);

    cudaFuncSetAttribute(gemm_tf32,
                         cudaFuncAttributeMaxDynamicSharedMemorySize, GEMM_SMEM);
    cudaFuncSetAttribute(flash_mma,
                         cudaFuncAttributeMaxDynamicSharedMemorySize, FL_SMEM);

    // Projections (round outputs to tf32 for flash's raw fragment loads)
    gemm_tf32<<<dim3(D_ / 128, (B_ * QL_) / 128), 256, GEMM_SMEM>>>(
        inq, Wq, bq, Qp, B_ * QL_, D_, D_, 1);
    gemm_tf32<<<dim3(D_ / 128, (B_ * KL_) / 128), 256, GEMM_SMEM>>>(
        ink, Wk, bk, Kp, B_ * KL_, D_, D_, 1);
    gemm_tf32<<<dim3(D_ / 128, (B_ * KL_) / 128), 256, GEMM_SMEM>>>(
        invv, Wv, bv, Vp, B_ * KL_, D_, D_, 1);

    // Attention (tensor-core flash)
    flash_mma<<<dim3(B_ * H_, QL_ / QT), 256, FL_SMEM>>>(mask, Op);

    // Output projection (full fp32 store)
    gemm_tf32<<<dim3(D_ / 128, (B_ * QL_) / 128), 256, GEMM_SMEM>>>(
        Op, Wf, bf, out, B_ * QL_, D_, D_, 0);
}